// round 12
// baseline (speedup 1.0000x reference)
#include <cuda_runtime.h>
#include <math.h>

#define DT 0.05f
#define NSTEPS 4
#define NTHREADS 256
#define PTS 32          // points per block (8 threads each)
#define TSTR 20         // tile row stride (floats): conflict-free, 16B aligned
#define PPB 836         // tile 320 + Ws 256 + Fs 256 + pad (mod 32 == 4)
#define TILE_OFF 0
#define W_OFF 320       // W stash (own rows)
#define F_OFF 576       // S0 initially, then F accumulator
#define SMEM_BYTES (PTS * PPB * 4)

typedef unsigned long long u64;

__device__ __forceinline__ u64 pack2(float x, float y) {
    u64 r;
    asm("mov.b64 %0, {%1, %2};" : "=l"(r) : "f"(x), "f"(y));
    return r;
}
__device__ __forceinline__ void unpack2(u64 v, float& x, float& y) {
    asm("mov.b64 {%0, %1}, %2;" : "=f"(x), "=f"(y) : "l"(v));
}
__device__ __forceinline__ void fma2(u64& d, u64 a, u64 b) {
    asm("fma.rn.f32x2 %0, %1, %2, %0;" : "+l"(d) : "l"(a), "l"(b));
}

__device__ __forceinline__ void put2(float* tile, int q, const float v0[16],
                                     const float v1[16]) {
    __syncwarp();
    float4* d0 = (float4*)(tile + q * TSTR);
    float4* d1 = (float4*)(tile + (q + 8) * TSTR);
    d0[0] = make_float4(v0[0], v0[1], v0[2], v0[3]);
    d0[1] = make_float4(v0[4], v0[5], v0[6], v0[7]);
    d0[2] = make_float4(v0[8], v0[9], v0[10], v0[11]);
    d0[3] = make_float4(v0[12], v0[13], v0[14], v0[15]);
    d1[0] = make_float4(v1[0], v1[1], v1[2], v1[3]);
    d1[1] = make_float4(v1[4], v1[5], v1[6], v1[7]);
    d1[2] = make_float4(v1[8], v1[9], v1[10], v1[11]);
    d1[3] = make_float4(v1[12], v1[13], v1[14], v1[15]);
    __syncwarp();
}

// c{0,1} = a{0,1} * B. c, a distinct. LIVENESS INVARIANT: at every call site
// at most these two row-pairs are live (96 floats incl. acc) — exceeding that
// spills at the 128-reg cap (root cause of R8-R11 DRAM blowup).
template <int BSTR>
__device__ __forceinline__ void mm2z(float c0[16], float c1[16],
                                     const float a0[16], const float a1[16],
                                     const float* Bs) {
    u64 acc0[8], acc1[8];
#pragma unroll
    for (int i = 0; i < 8; i++) { acc0[i] = 0ULL; acc1[i] = 0ULL; }
#pragma unroll
    for (int k = 0; k < 16; k++) {
        const ulonglong2* bp = (const ulonglong2*)(Bs + k * BSTR);
        ulonglong2 ba = bp[0], bb = bp[1], bc = bp[2], bd = bp[3];
        u64 ak0 = pack2(a0[k], a0[k]);
        u64 ak1 = pack2(a1[k], a1[k]);
        fma2(acc0[0], ak0, ba.x); fma2(acc0[1], ak0, ba.y);
        fma2(acc0[2], ak0, bb.x); fma2(acc0[3], ak0, bb.y);
        fma2(acc0[4], ak0, bc.x); fma2(acc0[5], ak0, bc.y);
        fma2(acc0[6], ak0, bd.x); fma2(acc0[7], ak0, bd.y);
        fma2(acc1[0], ak1, ba.x); fma2(acc1[1], ak1, ba.y);
        fma2(acc1[2], ak1, bb.x); fma2(acc1[3], ak1, bb.y);
        fma2(acc1[4], ak1, bc.x); fma2(acc1[5], ak1, bc.y);
        fma2(acc1[6], ak1, bd.x); fma2(acc1[7], ak1, bd.y);
    }
#pragma unroll
    for (int i = 0; i < 8; i++) {
        unpack2(acc0[i], c0[2 * i], c0[2 * i + 1]);
        unpack2(acc1[i], c1[2 * i], c1[2 * i + 1]);
    }
}

// c{0,1} += a{0,1} * B. c, a distinct. Same liveness invariant.
template <int BSTR>
__device__ __forceinline__ void mm2a(float c0[16], float c1[16],
                                     const float a0[16], const float a1[16],
                                     const float* Bs) {
    u64 acc0[8], acc1[8];
#pragma unroll
    for (int i = 0; i < 8; i++) {
        acc0[i] = pack2(c0[2 * i], c0[2 * i + 1]);
        acc1[i] = pack2(c1[2 * i], c1[2 * i + 1]);
    }
#pragma unroll
    for (int k = 0; k < 16; k++) {
        const ulonglong2* bp = (const ulonglong2*)(Bs + k * BSTR);
        ulonglong2 ba = bp[0], bb = bp[1], bc = bp[2], bd = bp[3];
        u64 ak0 = pack2(a0[k], a0[k]);
        u64 ak1 = pack2(a1[k], a1[k]);
        fma2(acc0[0], ak0, ba.x); fma2(acc0[1], ak0, ba.y);
        fma2(acc0[2], ak0, bb.x); fma2(acc0[3], ak0, bb.y);
        fma2(acc0[4], ak0, bc.x); fma2(acc0[5], ak0, bc.y);
        fma2(acc0[6], ak0, bd.x); fma2(acc0[7], ak0, bd.y);
        fma2(acc1[0], ak1, ba.x); fma2(acc1[1], ak1, ba.y);
        fma2(acc1[2], ak1, bb.x); fma2(acc1[3], ak1, bb.y);
        fma2(acc1[4], ak1, bc.x); fma2(acc1[5], ak1, bc.y);
        fma2(acc1[6], ak1, bd.x); fma2(acc1[7], ak1, bd.y);
    }
#pragma unroll
    for (int i = 0; i < 8; i++) {
        unpack2(acc0[i], c0[2 * i], c0[2 * i + 1]);
        unpack2(acc1[i], c1[2 * i], c1[2 * i + 1]);
    }
}

__device__ __forceinline__ void ld_row16(float v[16], const float* src) {
    const float4* s = (const float4*)src;
#pragma unroll
    for (int i = 0; i < 4; i++) {
        float4 t = s[i];
        v[4 * i + 0] = t.x; v[4 * i + 1] = t.y;
        v[4 * i + 2] = t.z; v[4 * i + 3] = t.w;
    }
}
__device__ __forceinline__ void st_row16(float* dst, const float v[16]) {
    float4* d = (float4*)dst;
    d[0] = make_float4(v[0], v[1], v[2], v[3]);
    d[1] = make_float4(v[4], v[5], v[6], v[7]);
    d[2] = make_float4(v[8], v[9], v[10], v[11]);
    d[3] = make_float4(v[12], v[13], v[14], v[15]);
}

// kick: W <- W - dt*W^2   (live: W, T, acc)
#define KICK()                                                               \
    do {                                                                     \
        put2(tile, q, W0, W1);                                               \
        _Pragma("unroll")                                                    \
        for (int j = 0; j < 16; j++) { T0[j] = -DT * W0[j]; T1[j] = -DT * W1[j]; } \
        mm2a<TSTR>(W0, W1, T0, T1, tile);                                    \
    } while (0)

// E-section: entry: W regs = W, Ws = W (stashed). Exit: tile = E = exp(2dt*W)
// (Taylor4(dt*W))^2. W regs are CONSUMED (dead). Only T,G live at any mm.
#define E_SECTION()                                                          \
    do {                                                                     \
        _Pragma("unroll")                                                    \
        for (int j = 0; j < 16; j++) { T0[j] = DT * W0[j]; T1[j] = DT * W1[j]; } \
        put2(tile, q, T0, T1);                   /* tile <- Y = dt*W; W dead */ \
        mm2z<TSTR>(G0, G1, T0, T1, tile);        /* G = Y^2 */               \
        _Pragma("unroll")                                                    \
        for (int j = 0; j < 16; j++) {                                       \
            T0[j] = fmaf(1.0f / 24.0f, G0[j], (1.0f / 6.0f) * T0[j]);        \
            T1[j] = fmaf(1.0f / 24.0f, G1[j], (1.0f / 6.0f) * T1[j]);        \
        }                                                                    \
        T0[q] += 0.5f; T1[r1] += 0.5f;                                       \
        put2(tile, q, T0, T1);                   /* tile <- U */             \
        ld_row16(T0, Ws + q * 16);               /* reload W (own rows) */   \
        ld_row16(T1, Ws + r1 * 16);                                          \
        _Pragma("unroll")                                                    \
        for (int j = 0; j < 16; j++) { T0[j] *= DT; T1[j] *= DT; }           \
        T0[q] += 1.0f; T1[r1] += 1.0f;           /* T = I + dt*W */          \
        mm2a<TSTR>(T0, T1, G0, G1, tile);        /* T = E4 */                \
        put2(tile, q, T0, T1);                   /* tile <- E4 */            \
        mm2z<TSTR>(G0, G1, T0, T1, tile);        /* G = E4^2 = E */          \
        put2(tile, q, G0, G1);                   /* tile <- E */             \
    } while (0)

__global__ void __launch_bounds__(NTHREADS, 2)
ham_kernel(const float* __restrict__ mu, const float* __restrict__ Sigma,
           const float* __restrict__ phi, const float* __restrict__ pi_mu,
           const float* __restrict__ pi_Sigma, const float* __restrict__ pi_phi,
           const float* __restrict__ M_inv,
           float* __restrict__ mu_o, float* __restrict__ Sig_o,
           float* __restrict__ phi_o) {
    extern __shared__ float smem[];
    const int tid = threadIdx.x;
    const int lp = tid >> 3;   // local point 0..31
    const int q = tid & 7;     // owns rows q and q+8
    const int r1 = q + 8;
    const int p = blockIdx.x * PTS + lp;
    float* tile = smem + lp * PPB + TILE_OFF;
    float* Ws = smem + lp * PPB + W_OFF;   // stride 16
    float* Fs = smem + lp * PPB + F_OFF;   // stride 16

    float W0[16], W1[16], T0[16], T1[16], G0[16], G1[16];

    // ---- S0 -> Fs (temporary home); P -> T ----
    ld_row16(T0, Sigma + (size_t)p * 256 + q * 16);
    ld_row16(T1, Sigma + (size_t)p * 256 + r1 * 16);
    st_row16(Fs + q * 16, T0);
    st_row16(Fs + r1 * 16, T1);
    ld_row16(T0, pi_Sigma + (size_t)p * 256 + q * 16);
    ld_row16(T1, pi_Sigma + (size_t)p * 256 + r1 * 16);

    // ---- mu update: mu + NSTEPS*dt * M_inv @ pi_mu ----
    {
        float pmv[16];
        ld_row16(pmv, pi_mu + (size_t)p * 16);
        const float* M0 = M_inv + (size_t)p * 256 + q * 16;
        const float* M1 = M_inv + (size_t)p * 256 + r1 * 16;
        float s0 = 0.0f, s1 = 0.0f;
#pragma unroll
        for (int j = 0; j < 16; j++) {
            s0 = fmaf(M0[j], pmv[j], s0);
            s1 = fmaf(M1[j], pmv[j], s1);
        }
        mu_o[(size_t)p * 16 + q]  = mu[(size_t)p * 16 + q]  + ((float)NSTEPS * DT) * s0;
        mu_o[(size_t)p * 16 + r1] = mu[(size_t)p * 16 + r1] + ((float)NSTEPS * DT) * s1;
    }

    // ---- phi update (thread q==0 of each point) ----
    if (q == 0) {
        float px = phi[p * 3 + 0], py = phi[p * 3 + 1], pz = phi[p * 3 + 2];
        const float vx = pi_phi[p * 3 + 0];
        const float vy = pi_phi[p * 3 + 1];
        const float vz = pi_phi[p * 3 + 2];
        const float TWO_PI = 6.283185307179586f;
        const float PI_F = 3.141592653589793f;
        const float R_MAX = 3.131592653589793f;
#pragma unroll 1
        for (int s = 0; s < NSTEPS; s++) {
            px += DT * vx; py += DT * vy; pz += DT * vz;
            float th = sqrtf(px * px + py * py + pz * pz);
            float ths = fmaxf(th, 1e-12f);
            float inv = 1.0f / ths;
            float ax = px * inv, ay = py * inv, az = pz * inv;
            float tw = fmodf(th, TWO_PI);
            bool flip = tw > PI_F;
            float tf = flip ? (TWO_PI - tw) : tw;
            if (flip) { ax = -ax; ay = -ay; az = -az; }
            tf = fminf(tf, R_MAX);
            px = ax * tf; py = ay * tf; pz = az * tf;
        }
        phi_o[p * 3 + 0] = px;
        phi_o[p * 3 + 1] = py;
        phi_o[p * 3 + 2] = pz;
    }
    __syncwarp();  // S0 (in Fs) visible to all threads of the point

    // ===== peel step 0 =====
    mm2z<16>(W0, W1, T0, T1, Fs);                // W = P * S0
    KICK();                                      // kick1
    st_row16(Ws + q * 16, W0);                   // stash W (own rows)
    st_row16(Ws + r1 * 16, W1);
    E_SECTION();                                 // tile = E0 (W regs dead)
    st_row16(Fs + q * 16, G0);                   // F := E0 (own rows)
    st_row16(Fs + r1 * 16, G1);

    // ===== steps 1..3: uniform, branch-free =====
#pragma unroll 1
    for (int step = 1; step < NSTEPS; step++) {
        // W <- W_old * E_prev  (tile = E_prev; W_old from Ws)
        ld_row16(T0, Ws + q * 16);
        ld_row16(T1, Ws + r1 * 16);
        mm2z<TSTR>(W0, W1, T0, T1, tile);
        KICK();                                  // kick2 of prev step
        KICK();                                  // kick1 of this step
        st_row16(Ws + q * 16, W0);               // stash W
        st_row16(Ws + r1 * 16, W1);
        E_SECTION();                             // tile = E_step
        // F <- F * E_step
        ld_row16(T0, Fs + q * 16);
        ld_row16(T1, Fs + r1 * 16);
        mm2z<TSTR>(G0, G1, T0, T1, tile);
        st_row16(Fs + q * 16, G0);
        st_row16(Fs + r1 * 16, G1);
    }

    // ===== final: S_out = sym(S0 * F) =====
    ld_row16(T0, Sigma + (size_t)p * 256 + q * 16);   // S0 rows (L2)
    ld_row16(T1, Sigma + (size_t)p * 256 + r1 * 16);
    __syncwarp();                                // all F rows written
    mm2z<16>(W0, W1, T0, T1, Fs);                // W = S0 * F
    put2(tile, q, W0, W1);                       // tile <- S_new (transpose)
#pragma unroll
    for (int j = 0; j < 16; j++) {
        W0[j] = 0.5f * (W0[j] + tile[j * TSTR + q]);
        W1[j] = 0.5f * (W1[j] + tile[j * TSTR + r1]);
    }
    st_row16(Sig_o + (size_t)p * 256 + q * 16, W0);
    st_row16(Sig_o + (size_t)p * 256 + r1 * 16, W1);
}

extern "C" void kernel_launch(void* const* d_in, const int* in_sizes, int n_in,
                              void* d_out, int out_size) {
    const float* mu       = (const float*)d_in[0];
    const float* Sigma    = (const float*)d_in[1];
    const float* phi      = (const float*)d_in[2];
    const float* pi_mu    = (const float*)d_in[3];
    const float* pi_Sigma = (const float*)d_in[4];
    const float* pi_phi   = (const float*)d_in[5];
    const float* M_inv    = (const float*)d_in[6];

    const int npts = in_sizes[0] / 16;  // B*N = 32768
    float* out = (float*)d_out;
    float* mu_o  = out;
    float* Sig_o = out + (size_t)npts * 16;
    float* phi_o = out + (size_t)npts * 16 + (size_t)npts * 256;

    cudaFuncSetAttribute(ham_kernel, cudaFuncAttributeMaxDynamicSharedMemorySize,
                         SMEM_BYTES);

    dim3 grid(npts / PTS);
    dim3 block(NTHREADS);
    ham_kernel<<<grid, block, SMEM_BYTES>>>(mu, Sigma, phi, pi_mu, pi_Sigma,
                                            pi_phi, M_inv, mu_o, Sig_o, phi_o);
}

// round 13
// speedup vs baseline: 1.4056x; 1.4056x over previous
#include <cuda_runtime.h>
#include <math.h>

#define DT 0.05f
#define NSTEPS 4
#define NTHREADS 128
#define PTS 16          // points per block (8 threads each)
#define TSTR 20         // tile row stride (floats): conflict-free, 16B aligned
#define PPB 836         // tile 320 + Ws 256 + Fs 256 + pad (mod 32 == 4)
#define TILE_OFF 0
#define W_OFF 320       // W stash (own rows)
#define F_OFF 576       // S0 initially, then F accumulator
#define SMEM_BYTES (PTS * PPB * 4)

typedef unsigned long long u64;

__device__ __forceinline__ u64 pack2(float x, float y) {
    u64 r;
    asm("mov.b64 %0, {%1, %2};" : "=l"(r) : "f"(x), "f"(y));
    return r;
}
__device__ __forceinline__ void unpack2(u64 v, float& x, float& y) {
    asm("mov.b64 {%0, %1}, %2;" : "=f"(x), "=f"(y) : "l"(v));
}
__device__ __forceinline__ void fma2(u64& d, u64 a, u64 b) {
    asm("fma.rn.f32x2 %0, %1, %2, %0;" : "+l"(d) : "l"(a), "l"(b));
}

__device__ __forceinline__ void put2(float* tile, int q, const float v0[16],
                                     const float v1[16]) {
    __syncwarp();
    float4* d0 = (float4*)(tile + q * TSTR);
    float4* d1 = (float4*)(tile + (q + 8) * TSTR);
    d0[0] = make_float4(v0[0], v0[1], v0[2], v0[3]);
    d0[1] = make_float4(v0[4], v0[5], v0[6], v0[7]);
    d0[2] = make_float4(v0[8], v0[9], v0[10], v0[11]);
    d0[3] = make_float4(v0[12], v0[13], v0[14], v0[15]);
    d1[0] = make_float4(v1[0], v1[1], v1[2], v1[3]);
    d1[1] = make_float4(v1[4], v1[5], v1[6], v1[7]);
    d1[2] = make_float4(v1[8], v1[9], v1[10], v1[11]);
    d1[3] = make_float4(v1[12], v1[13], v1[14], v1[15]);
    __syncwarp();
}

// c{0,1} = a{0,1} * B. c, a distinct arrays.
template <int BSTR>
__device__ __forceinline__ void mm2z(float c0[16], float c1[16],
                                     const float a0[16], const float a1[16],
                                     const float* Bs) {
    u64 acc0[8], acc1[8];
#pragma unroll
    for (int i = 0; i < 8; i++) { acc0[i] = 0ULL; acc1[i] = 0ULL; }
#pragma unroll
    for (int k = 0; k < 16; k++) {
        const ulonglong2* bp = (const ulonglong2*)(Bs + k * BSTR);
        ulonglong2 ba = bp[0], bb = bp[1], bc = bp[2], bd = bp[3];
        u64 ak0 = pack2(a0[k], a0[k]);
        u64 ak1 = pack2(a1[k], a1[k]);
        fma2(acc0[0], ak0, ba.x); fma2(acc0[1], ak0, ba.y);
        fma2(acc0[2], ak0, bb.x); fma2(acc0[3], ak0, bb.y);
        fma2(acc0[4], ak0, bc.x); fma2(acc0[5], ak0, bc.y);
        fma2(acc0[6], ak0, bd.x); fma2(acc0[7], ak0, bd.y);
        fma2(acc1[0], ak1, ba.x); fma2(acc1[1], ak1, ba.y);
        fma2(acc1[2], ak1, bb.x); fma2(acc1[3], ak1, bb.y);
        fma2(acc1[4], ak1, bc.x); fma2(acc1[5], ak1, bc.y);
        fma2(acc1[6], ak1, bd.x); fma2(acc1[7], ak1, bd.y);
    }
#pragma unroll
    for (int i = 0; i < 8; i++) {
        unpack2(acc0[i], c0[2 * i], c0[2 * i + 1]);
        unpack2(acc1[i], c1[2 * i], c1[2 * i + 1]);
    }
}

// c{0,1} += a{0,1} * B. c, a distinct arrays.
template <int BSTR>
__device__ __forceinline__ void mm2a(float c0[16], float c1[16],
                                     const float a0[16], const float a1[16],
                                     const float* Bs) {
    u64 acc0[8], acc1[8];
#pragma unroll
    for (int i = 0; i < 8; i++) {
        acc0[i] = pack2(c0[2 * i], c0[2 * i + 1]);
        acc1[i] = pack2(c1[2 * i], c1[2 * i + 1]);
    }
#pragma unroll
    for (int k = 0; k < 16; k++) {
        const ulonglong2* bp = (const ulonglong2*)(Bs + k * BSTR);
        ulonglong2 ba = bp[0], bb = bp[1], bc = bp[2], bd = bp[3];
        u64 ak0 = pack2(a0[k], a0[k]);
        u64 ak1 = pack2(a1[k], a1[k]);
        fma2(acc0[0], ak0, ba.x); fma2(acc0[1], ak0, ba.y);
        fma2(acc0[2], ak0, bb.x); fma2(acc0[3], ak0, bb.y);
        fma2(acc0[4], ak0, bc.x); fma2(acc0[5], ak0, bc.y);
        fma2(acc0[6], ak0, bd.x); fma2(acc0[7], ak0, bd.y);
        fma2(acc1[0], ak1, ba.x); fma2(acc1[1], ak1, ba.y);
        fma2(acc1[2], ak1, bb.x); fma2(acc1[3], ak1, bb.y);
        fma2(acc1[4], ak1, bc.x); fma2(acc1[5], ak1, bc.y);
        fma2(acc1[6], ak1, bd.x); fma2(acc1[7], ak1, bd.y);
    }
#pragma unroll
    for (int i = 0; i < 8; i++) {
        unpack2(acc0[i], c0[2 * i], c0[2 * i + 1]);
        unpack2(acc1[i], c1[2 * i], c1[2 * i + 1]);
    }
}

__device__ __forceinline__ void ld_row16(float v[16], const float* src) {
    const float4* s = (const float4*)src;
#pragma unroll
    for (int i = 0; i < 4; i++) {
        float4 t = s[i];
        v[4 * i + 0] = t.x; v[4 * i + 1] = t.y;
        v[4 * i + 2] = t.z; v[4 * i + 3] = t.w;
    }
}
__device__ __forceinline__ void st_row16(float* dst, const float v[16]) {
    float4* d = (float4*)dst;
    d[0] = make_float4(v[0], v[1], v[2], v[3]);
    d[1] = make_float4(v[4], v[5], v[6], v[7]);
    d[2] = make_float4(v[8], v[9], v[10], v[11]);
    d[3] = make_float4(v[12], v[13], v[14], v[15]);
}

// kick: W <- W - dt*W^2
#define KICK()                                                               \
    do {                                                                     \
        put2(tile, q, W0, W1);                                               \
        _Pragma("unroll")                                                    \
        for (int j = 0; j < 16; j++) { T0[j] = -DT * W0[j]; T1[j] = -DT * W1[j]; } \
        mm2a<TSTR>(W0, W1, T0, T1, tile);                                    \
    } while (0)

// E-section: entry: W regs = W, Ws = W (stashed). Exit: tile = E = exp(2dt*W)
// via (Taylor4(dt*W))^2. W regs consumed.
#define E_SECTION()                                                          \
    do {                                                                     \
        _Pragma("unroll")                                                    \
        for (int j = 0; j < 16; j++) { T0[j] = DT * W0[j]; T1[j] = DT * W1[j]; } \
        put2(tile, q, T0, T1);                   /* tile <- Y = dt*W */      \
        mm2z<TSTR>(G0, G1, T0, T1, tile);        /* G = Y^2 */               \
        _Pragma("unroll")                                                    \
        for (int j = 0; j < 16; j++) {                                       \
            T0[j] = fmaf(1.0f / 24.0f, G0[j], (1.0f / 6.0f) * T0[j]);        \
            T1[j] = fmaf(1.0f / 24.0f, G1[j], (1.0f / 6.0f) * T1[j]);        \
        }                                                                    \
        T0[q] += 0.5f; T1[r1] += 0.5f;                                       \
        put2(tile, q, T0, T1);                   /* tile <- U */             \
        ld_row16(T0, Ws + q * 16);               /* reload W (own rows) */   \
        ld_row16(T1, Ws + r1 * 16);                                          \
        _Pragma("unroll")                                                    \
        for (int j = 0; j < 16; j++) { T0[j] *= DT; T1[j] *= DT; }           \
        T0[q] += 1.0f; T1[r1] += 1.0f;           /* T = I + dt*W */          \
        mm2a<TSTR>(T0, T1, G0, G1, tile);        /* T = E4 */                \
        put2(tile, q, T0, T1);                   /* tile <- E4 */            \
        mm2z<TSTR>(G0, G1, T0, T1, tile);        /* G = E4^2 = E */          \
        put2(tile, q, G0, G1);                   /* tile <- E */             \
    } while (0)

__global__ void __launch_bounds__(NTHREADS, 2)
ham_kernel(const float* __restrict__ mu, const float* __restrict__ Sigma,
           const float* __restrict__ phi, const float* __restrict__ pi_mu,
           const float* __restrict__ pi_Sigma, const float* __restrict__ pi_phi,
           const float* __restrict__ M_inv,
           float* __restrict__ mu_o, float* __restrict__ Sig_o,
           float* __restrict__ phi_o) {
    extern __shared__ float smem[];
    const int tid = threadIdx.x;
    const int lp = tid >> 3;   // local point 0..15
    const int q = tid & 7;     // owns rows q and q+8
    const int r1 = q + 8;
    const int p = blockIdx.x * PTS + lp;
    float* tile = smem + lp * PPB + TILE_OFF;
    float* Ws = smem + lp * PPB + W_OFF;   // stride 16
    float* Fs = smem + lp * PPB + F_OFF;   // stride 16

    float W0[16], W1[16], T0[16], T1[16], G0[16], G1[16];

    // ---- S0 -> Fs (temporary home); P -> T ----
    ld_row16(T0, Sigma + (size_t)p * 256 + q * 16);
    ld_row16(T1, Sigma + (size_t)p * 256 + r1 * 16);
    st_row16(Fs + q * 16, T0);
    st_row16(Fs + r1 * 16, T1);
    ld_row16(T0, pi_Sigma + (size_t)p * 256 + q * 16);
    ld_row16(T1, pi_Sigma + (size_t)p * 256 + r1 * 16);

    // ---- mu update: mu + NSTEPS*dt * M_inv @ pi_mu ----
    {
        float pmv[16];
        ld_row16(pmv, pi_mu + (size_t)p * 16);
        const float* M0 = M_inv + (size_t)p * 256 + q * 16;
        const float* M1 = M_inv + (size_t)p * 256 + r1 * 16;
        float s0 = 0.0f, s1 = 0.0f;
#pragma unroll
        for (int j = 0; j < 16; j++) {
            s0 = fmaf(M0[j], pmv[j], s0);
            s1 = fmaf(M1[j], pmv[j], s1);
        }
        mu_o[(size_t)p * 16 + q]  = mu[(size_t)p * 16 + q]  + ((float)NSTEPS * DT) * s0;
        mu_o[(size_t)p * 16 + r1] = mu[(size_t)p * 16 + r1] + ((float)NSTEPS * DT) * s1;
    }

    // ---- phi update (thread q==0 of each point) ----
    if (q == 0) {
        float px = phi[p * 3 + 0], py = phi[p * 3 + 1], pz = phi[p * 3 + 2];
        const float vx = pi_phi[p * 3 + 0];
        const float vy = pi_phi[p * 3 + 1];
        const float vz = pi_phi[p * 3 + 2];
        const float TWO_PI = 6.283185307179586f;
        const float PI_F = 3.141592653589793f;
        const float R_MAX = 3.131592653589793f;
#pragma unroll 1
        for (int s = 0; s < NSTEPS; s++) {
            px += DT * vx; py += DT * vy; pz += DT * vz;
            float th = sqrtf(px * px + py * py + pz * pz);
            float ths = fmaxf(th, 1e-12f);
            float inv = 1.0f / ths;
            float ax = px * inv, ay = py * inv, az = pz * inv;
            float tw = fmodf(th, TWO_PI);
            bool flip = tw > PI_F;
            float tf = flip ? (TWO_PI - tw) : tw;
            if (flip) { ax = -ax; ay = -ay; az = -az; }
            tf = fminf(tf, R_MAX);
            px = ax * tf; py = ay * tf; pz = az * tf;
        }
        phi_o[p * 3 + 0] = px;
        phi_o[p * 3 + 1] = py;
        phi_o[p * 3 + 2] = pz;
    }
    __syncwarp();  // S0 (in Fs) visible to all threads of the point

    // ===== peel step 0 =====
    mm2z<16>(W0, W1, T0, T1, Fs);                // W = P * S0
    KICK();                                      // kick1
    st_row16(Ws + q * 16, W0);                   // stash W (own rows)
    st_row16(Ws + r1 * 16, W1);
    E_SECTION();                                 // tile = E0
    st_row16(Fs + q * 16, G0);                   // F := E0 (own rows)
    st_row16(Fs + r1 * 16, G1);

    // ===== steps 1..3: uniform, branch-free =====
#pragma unroll 1
    for (int step = 1; step < NSTEPS; step++) {
        ld_row16(T0, Ws + q * 16);               // W_old
        ld_row16(T1, Ws + r1 * 16);
        mm2z<TSTR>(W0, W1, T0, T1, tile);        // W <- W_old * E_prev
        KICK();                                  // kick2 of prev step
        KICK();                                  // kick1 of this step
        st_row16(Ws + q * 16, W0);               // stash W
        st_row16(Ws + r1 * 16, W1);
        E_SECTION();                             // tile = E_step
        ld_row16(T0, Fs + q * 16);               // F
        ld_row16(T1, Fs + r1 * 16);
        mm2z<TSTR>(G0, G1, T0, T1, tile);        // F <- F * E_step
        st_row16(Fs + q * 16, G0);
        st_row16(Fs + r1 * 16, G1);
    }

    // ===== final: S_out = sym(S0 * F) =====
    ld_row16(T0, Sigma + (size_t)p * 256 + q * 16);   // S0 rows (L2)
    ld_row16(T1, Sigma + (size_t)p * 256 + r1 * 16);
    __syncwarp();                                // all F rows written
    mm2z<16>(W0, W1, T0, T1, Fs);                // W = S0 * F
    put2(tile, q, W0, W1);                       // tile <- S_new (transpose)
#pragma unroll
    for (int j = 0; j < 16; j++) {
        W0[j] = 0.5f * (W0[j] + tile[j * TSTR + q]);
        W1[j] = 0.5f * (W1[j] + tile[j * TSTR + r1]);
    }
    st_row16(Sig_o + (size_t)p * 256 + q * 16, W0);
    st_row16(Sig_o + (size_t)p * 256 + r1 * 16, W1);
}

extern "C" void kernel_launch(void* const* d_in, const int* in_sizes, int n_in,
                              void* d_out, int out_size) {
    const float* mu       = (const float*)d_in[0];
    const float* Sigma    = (const float*)d_in[1];
    const float* phi      = (const float*)d_in[2];
    const float* pi_mu    = (const float*)d_in[3];
    const float* pi_Sigma = (const float*)d_in[4];
    const float* pi_phi   = (const float*)d_in[5];
    const float* M_inv    = (const float*)d_in[6];

    const int npts = in_sizes[0] / 16;  // B*N = 32768
    float* out = (float*)d_out;
    float* mu_o  = out;
    float* Sig_o = out + (size_t)npts * 16;
    float* phi_o = out + (size_t)npts * 16 + (size_t)npts * 256;

    cudaFuncSetAttribute(ham_kernel, cudaFuncAttributeMaxDynamicSharedMemorySize,
                         SMEM_BYTES);

    dim3 grid(npts / PTS);
    dim3 block(NTHREADS);
    ham_kernel<<<grid, block, SMEM_BYTES>>>(mu, Sigma, phi, pi_mu, pi_Sigma,
                                            pi_phi, M_inv, mu_o, Sig_o, phi_o);
}